// round 1
// baseline (speedup 1.0000x reference)
#include <cuda_runtime.h>
#include <math.h>
#include <stdint.h>

// Problem constants
#define BB 256
#define TT 128
#define EE 300
#define HH 2048
#define GG 8192   // 4*H

// Scratch (device globals -- no allocation allowed)
__device__ float g_xg[(size_t)BB * TT * GG];   // [B*T, 4H] precomputed input gates (1 GiB)
__device__ float g_gates[(size_t)BB * GG];     // per-step gate pre-activations
__device__ float g_h[(size_t)BB * HH];
__device__ float g_c[(size_t)BB * HH];

// ---------------------------------------------------------------------------
// Zero h, c each launch (graph replays must be deterministic)
// ---------------------------------------------------------------------------
__global__ void init_state_kernel() {
    int i = blockIdx.x * blockDim.x + threadIdx.x;
    if (i < BB * HH) { g_h[i] = 0.0f; g_c[i] = 0.0f; }
}

// ---------------------------------------------------------------------------
// Generic NT GEMM: C[m, n] = sum_k A[m,k] * Bm[n,k]  (+ bias[n]) (+ addend[m,n])
//   A row stride == K, Bm row stride == K, C row stride == GG (8192)
//   BM=BN=128, BK=8, 256 threads, 8x8 per thread.
//   Requires: M,N multiples of 128; K multiple of 4.
// ---------------------------------------------------------------------------
__global__ void __launch_bounds__(256) gemm_nt_128(
    const float* __restrict__ A,
    const float* __restrict__ Bm,
    float* __restrict__ C,
    int K,
    const float* __restrict__ bias0,   // per-column, nullable
    const float* __restrict__ bias1,   // per-column, nullable
    const float* __restrict__ addend,  // [M rows, stride addStride], nullable
    int addStride)
{
    __shared__ float As[8][128];
    __shared__ float Bs[8][128];

    const int tid = threadIdx.x;
    const int tx = tid & 15;        // 0..15 -> N direction
    const int ty = tid >> 4;        // 0..15 -> M direction
    const int tileN = blockIdx.x * 128;
    const int tileM = blockIdx.y * 128;

    const int lrow = tid >> 1;          // 0..127 row loaded by this thread
    const int lkb  = (tid & 1) * 4;     // 0 or 4, k sub-offset

    const float* Aptr = A + (size_t)(tileM + lrow) * K;
    const float* Bptr = Bm + (size_t)(tileN + lrow) * K;

    float acc[8][8];
#pragma unroll
    for (int i = 0; i < 8; i++)
#pragma unroll
        for (int j = 0; j < 8; j++) acc[i][j] = 0.0f;

    for (int k0 = 0; k0 < K; k0 += 8) {
        const int k = k0 + lkb;
        float4 av, bv;
        if (k < K) {   // K % 4 == 0 guarantees full float4 if k < K
            av = *(const float4*)(Aptr + k);
            bv = *(const float4*)(Bptr + k);
        } else {
            av = make_float4(0.f, 0.f, 0.f, 0.f);
            bv = make_float4(0.f, 0.f, 0.f, 0.f);
        }
        As[lkb + 0][lrow] = av.x;
        As[lkb + 1][lrow] = av.y;
        As[lkb + 2][lrow] = av.z;
        As[lkb + 3][lrow] = av.w;
        Bs[lkb + 0][lrow] = bv.x;
        Bs[lkb + 1][lrow] = bv.y;
        Bs[lkb + 2][lrow] = bv.z;
        Bs[lkb + 3][lrow] = bv.w;
        __syncthreads();

#pragma unroll
        for (int kk = 0; kk < 8; kk++) {
            float a[8], b[8];
            float4 a0 = *(const float4*)&As[kk][ty * 8];
            float4 a1 = *(const float4*)&As[kk][ty * 8 + 4];
            float4 b0 = *(const float4*)&Bs[kk][tx * 8];
            float4 b1 = *(const float4*)&Bs[kk][tx * 8 + 4];
            a[0]=a0.x; a[1]=a0.y; a[2]=a0.z; a[3]=a0.w;
            a[4]=a1.x; a[5]=a1.y; a[6]=a1.z; a[7]=a1.w;
            b[0]=b0.x; b[1]=b0.y; b[2]=b0.z; b[3]=b0.w;
            b[4]=b1.x; b[5]=b1.y; b[6]=b1.z; b[7]=b1.w;
#pragma unroll
            for (int i = 0; i < 8; i++)
#pragma unroll
                for (int j = 0; j < 8; j++)
                    acc[i][j] = fmaf(a[i], b[j], acc[i][j]);
        }
        __syncthreads();
    }

    // Epilogue
#pragma unroll
    for (int i = 0; i < 8; i++) {
        const int row = tileM + ty * 8 + i;
        const float* addRow = addend ? (addend + (size_t)row * addStride) : nullptr;
        float* Crow = C + (size_t)row * GG;
#pragma unroll
        for (int j = 0; j < 8; j++) {
            const int col = tileN + tx * 8 + j;
            float v = acc[i][j];
            if (bias0) v += bias0[col] + bias1[col];
            if (addRow) v += addRow[col];
            Crow[col] = v;
        }
    }
}

// ---------------------------------------------------------------------------
// Pointwise LSTM cell update: reads g_gates (pre-activations), updates g_h/g_c.
// out != nullptr on the final timestep -> also writes d_out.
// ---------------------------------------------------------------------------
__device__ __forceinline__ float sigmoidf_(float x) {
    return 1.0f / (1.0f + expf(-x));
}

__global__ void lstm_pointwise_kernel(float* __restrict__ out) {
    int idx = blockIdx.x * blockDim.x + threadIdx.x;
    if (idx >= BB * HH) return;
    const int b = idx >> 11;          // /H
    const int j = idx & (HH - 1);
    const float* gr = g_gates + (size_t)b * GG;
    const float vi = gr[j];
    const float vf = gr[HH + j];
    const float vg = gr[2 * HH + j];
    const float vo = gr[3 * HH + j];
    const float ig = sigmoidf_(vi);
    const float fg = sigmoidf_(vf);
    const float gg = tanhf(vg);
    const float og = sigmoidf_(vo);
    const float cn = fg * g_c[idx] + ig * gg;
    const float hn = og * tanhf(cn);
    g_c[idx] = cn;
    g_h[idx] = hn;
    if (out) out[idx] = hn;
}

// ---------------------------------------------------------------------------
// Launch
// ---------------------------------------------------------------------------
extern "C" void kernel_launch(void* const* d_in, const int* in_sizes, int n_in,
                              void* d_out, int out_size) {
    const float* x    = (const float*)d_in[0];   // [B, T, E]
    const float* W_ih = (const float*)d_in[1];   // [4H, E]
    const float* W_hh = (const float*)d_in[2];   // [4H, H]
    const float* b_ih = (const float*)d_in[3];   // [4H]
    const float* b_hh = (const float*)d_in[4];   // [4H]
    float* out = (float*)d_out;                  // [B, H]

    float *xg_p, *gates_p, *h_p;
    cudaGetSymbolAddress((void**)&xg_p, g_xg);
    cudaGetSymbolAddress((void**)&gates_p, g_gates);
    cudaGetSymbolAddress((void**)&h_p, g_h);

    // Reset recurrent state
    init_state_kernel<<<(BB * HH + 255) / 256, 256>>>();

    // Phase 1: xg[b*T+t, :] = x[b,t,:] @ W_ih^T + b_ih + b_hh
    {
        dim3 grid(GG / 128, (BB * TT) / 128);   // 64 x 256
        gemm_nt_128<<<grid, 256>>>(x, W_ih, xg_p, EE, b_ih, b_hh, nullptr, 0);
    }

    // Phase 2: recurrence
    for (int t = 0; t < TT; t++) {
        dim3 grid(GG / 128, BB / 128);          // 64 x 2
        // gates[b, :] = h[b,:] @ W_hh^T + xg[b*T + t, :]
        gemm_nt_128<<<grid, 256>>>(h_p, W_hh, gates_p, HH,
                                   nullptr, nullptr,
                                   xg_p + (size_t)t * GG, TT * GG);
        lstm_pointwise_kernel<<<(BB * HH + 255) / 256, 256>>>(
            (t == TT - 1) ? out : nullptr);
    }
}

// round 2
// speedup vs baseline: 1.5586x; 1.5586x over previous
#include <cuda_runtime.h>
#include <math.h>
#include <stdint.h>

// Problem constants
#define BB 256
#define TT 128
#define EE 300
#define HH 2048
#define GG 8192   // 4*H

// Scratch (device globals -- no allocation allowed)
__device__ float g_xg[(size_t)BB * TT * GG];   // [B*T, 4H] precomputed input gates (1 GiB)
__device__ float g_gates[(size_t)BB * GG];     // per-step gate pre-activations
__device__ float g_h[(size_t)BB * HH];
__device__ float g_c[(size_t)BB * HH];

// ---------------------------------------------------------------------------
// Zero h, c each launch (graph replays must be deterministic)
// ---------------------------------------------------------------------------
__global__ void init_state_kernel() {
    int i = blockIdx.x * blockDim.x + threadIdx.x;
    if (i < BB * HH) { g_h[i] = 0.0f; g_c[i] = 0.0f; }
}

// ---------------------------------------------------------------------------
// Generic NT GEMM: C[m, n] = sum_k A[m,k] * Bm[n,k]  (+ bias[n]) (+ addend[m,n])
//   A row stride == K, Bm row stride == K, C row stride == GG (8192)
//   BM=BN=128, BK=8, 256 threads, 8x8 per thread.
//   Requires: M,N multiples of 128; K multiple of 4.
// ---------------------------------------------------------------------------
__global__ void __launch_bounds__(256) gemm_nt_128(
    const float* __restrict__ A,
    const float* __restrict__ Bm,
    float* __restrict__ C,
    int K,
    const float* __restrict__ bias0,   // per-column, nullable
    const float* __restrict__ bias1,   // per-column, nullable
    const float* __restrict__ addend,  // [M rows, stride addStride], nullable
    int addStride)
{
    __shared__ float As[8][128];
    __shared__ float Bs[8][128];

    const int tid = threadIdx.x;
    const int tx = tid & 15;        // 0..15 -> N direction
    const int ty = tid >> 4;        // 0..15 -> M direction
    const int tileN = blockIdx.x * 128;
    const int tileM = blockIdx.y * 128;

    const int lrow = tid >> 1;          // 0..127 row loaded by this thread
    const int lkb  = (tid & 1) * 4;     // 0 or 4, k sub-offset

    const float* Aptr = A + (size_t)(tileM + lrow) * K;
    const float* Bptr = Bm + (size_t)(tileN + lrow) * K;

    float acc[8][8];
#pragma unroll
    for (int i = 0; i < 8; i++)
#pragma unroll
        for (int j = 0; j < 8; j++) acc[i][j] = 0.0f;

    for (int k0 = 0; k0 < K; k0 += 8) {
        const int k = k0 + lkb;
        float4 av, bv;
        if (k < K) {   // K % 4 == 0 guarantees full float4 if k < K
            av = *(const float4*)(Aptr + k);
            bv = *(const float4*)(Bptr + k);
        } else {
            av = make_float4(0.f, 0.f, 0.f, 0.f);
            bv = make_float4(0.f, 0.f, 0.f, 0.f);
        }
        As[lkb + 0][lrow] = av.x;
        As[lkb + 1][lrow] = av.y;
        As[lkb + 2][lrow] = av.z;
        As[lkb + 3][lrow] = av.w;
        Bs[lkb + 0][lrow] = bv.x;
        Bs[lkb + 1][lrow] = bv.y;
        Bs[lkb + 2][lrow] = bv.z;
        Bs[lkb + 3][lrow] = bv.w;
        __syncthreads();

#pragma unroll
        for (int kk = 0; kk < 8; kk++) {
            float a[8], b[8];
            float4 a0 = *(const float4*)&As[kk][ty * 8];
            float4 a1 = *(const float4*)&As[kk][ty * 8 + 4];
            float4 b0 = *(const float4*)&Bs[kk][tx * 8];
            float4 b1 = *(const float4*)&Bs[kk][tx * 8 + 4];
            a[0]=a0.x; a[1]=a0.y; a[2]=a0.z; a[3]=a0.w;
            a[4]=a1.x; a[5]=a1.y; a[6]=a1.z; a[7]=a1.w;
            b[0]=b0.x; b[1]=b0.y; b[2]=b0.z; b[3]=b0.w;
            b[4]=b1.x; b[5]=b1.y; b[6]=b1.z; b[7]=b1.w;
#pragma unroll
            for (int i = 0; i < 8; i++)
#pragma unroll
                for (int j = 0; j < 8; j++)
                    acc[i][j] = fmaf(a[i], b[j], acc[i][j]);
        }
        __syncthreads();
    }

    // Epilogue
#pragma unroll
    for (int i = 0; i < 8; i++) {
        const int row = tileM + ty * 8 + i;
        const float* addRow = addend ? (addend + (size_t)row * addStride) : nullptr;
        float* Crow = C + (size_t)row * GG;
#pragma unroll
        for (int j = 0; j < 8; j++) {
            const int col = tileN + tx * 8 + j;
            float v = acc[i][j];
            if (bias0) v += bias0[col] + bias1[col];
            if (addRow) v += addRow[col];
            Crow[col] = v;
        }
    }
}

// ---------------------------------------------------------------------------
// Pointwise LSTM cell update: reads g_gates (pre-activations), updates g_h/g_c.
// out != nullptr on the final timestep -> also writes d_out.
// ---------------------------------------------------------------------------
__device__ __forceinline__ float sigmoidf_(float x) {
    return 1.0f / (1.0f + expf(-x));
}

__global__ void lstm_pointwise_kernel(float* __restrict__ out) {
    int idx = blockIdx.x * blockDim.x + threadIdx.x;
    if (idx >= BB * HH) return;
    const int b = idx >> 11;          // /H
    const int j = idx & (HH - 1);
    const float* gr = g_gates + (size_t)b * GG;
    const float vi = gr[j];
    const float vf = gr[HH + j];
    const float vg = gr[2 * HH + j];
    const float vo = gr[3 * HH + j];
    const float ig = sigmoidf_(vi);
    const float fg = sigmoidf_(vf);
    const float gg = tanhf(vg);
    const float og = sigmoidf_(vo);
    const float cn = fg * g_c[idx] + ig * gg;
    const float hn = og * tanhf(cn);
    g_c[idx] = cn;
    g_h[idx] = hn;
    if (out) out[idx] = hn;
}

// ---------------------------------------------------------------------------
// Launch
// ---------------------------------------------------------------------------
extern "C" void kernel_launch(void* const* d_in, const int* in_sizes, int n_in,
                              void* d_out, int out_size) {
    const float* x    = (const float*)d_in[0];   // [B, T, E]
    const float* W_ih = (const float*)d_in[1];   // [4H, E]
    const float* W_hh = (const float*)d_in[2];   // [4H, H]
    const float* b_ih = (const float*)d_in[3];   // [4H]
    const float* b_hh = (const float*)d_in[4];   // [4H]
    float* out = (float*)d_out;                  // [B, H]

    float *xg_p, *gates_p, *h_p;
    cudaGetSymbolAddress((void**)&xg_p, g_xg);
    cudaGetSymbolAddress((void**)&gates_p, g_gates);
    cudaGetSymbolAddress((void**)&h_p, g_h);

    // Reset recurrent state
    init_state_kernel<<<(BB * HH + 255) / 256, 256>>>();

    // Phase 1: xg[b*T+t, :] = x[b,t,:] @ W_ih^T + b_ih + b_hh
    {
        dim3 grid(GG / 128, (BB * TT) / 128);   // 64 x 256
        gemm_nt_128<<<grid, 256>>>(x, W_ih, xg_p, EE, b_ih, b_hh, nullptr, 0);
    }

    // Phase 2: recurrence
    for (int t = 0; t < TT; t++) {
        dim3 grid(GG / 128, BB / 128);          // 64 x 2
        // gates[b, :] = h[b,:] @ W_hh^T + xg[b*T + t, :]
        gemm_nt_128<<<grid, 256>>>(h_p, W_hh, gates_p, HH,
                                   nullptr, nullptr,
                                   xg_p + (size_t)t * GG, TT * GG);
        lstm_pointwise_kernel<<<(BB * HH + 255) / 256, 256>>>(
            (t == TT - 1) ? out : nullptr);
    }
}